// round 6
// baseline (speedup 1.0000x reference)
#include <cuda_runtime.h>

// ContrastiveTreeLoss, single-launch fused version.
//
// Shapes (fixed by the problem instance):
//   arc_scores [B=512, N=256, N=256] f32
//   gold_heads [B, N] i32
//   mask       [B, N] i32
//   neg_heads  [K=4, B, N] i32
//   out        scalar f32 = mean_{k,b} relu(MARGIN - gold_total[b] + neg_total[k,b])
//
// One CTA per sentence computes the 5 tree scores and the per-sentence loss.
// The last CTA to finish (tracked by an atomic counter) reduces the 512
// per-sentence losses and writes the scalar, then resets the counter so the
// kernel is deterministic across CUDA-graph replays.

#define TL_B 512
#define TL_N 256
#define TL_K 4
#define TL_MARGIN 2.0f

__device__ float g_partial[TL_B];
__device__ unsigned int g_done_count;   // zero-initialized; reset each launch by last CTA

__global__ __launch_bounds__(TL_N, 4)
void tree_loss_fused_kernel(const float* __restrict__ arc,
                            const int*   __restrict__ gold,
                            const int*   __restrict__ mask,
                            const int*   __restrict__ neg,
                            float*       __restrict__ out)
{
    const int b = blockIdx.x;     // sentence
    const int d = threadIdx.x;    // dependent index 0..N-1 (d=0 unused)
    const float* __restrict__ arcb = arc + (size_t)b * TL_N * TL_N;

    float vals[TL_K + 1];
#pragma unroll
    for (int i = 0; i < TL_K + 1; i++) vals[i] = 0.0f;

    if (d >= 1) {
        const float m = (float)__ldg(&mask[b * TL_N + d]);
        int gh = __ldg(&gold[b * TL_N + d]);
        gh = min(max(gh, 0), TL_N - 1);
        vals[0] = __ldg(arcb + gh * TL_N + d) * m;      // arc[b, gh, d]
#pragma unroll
        for (int k = 0; k < TL_K; k++) {
            int nh = __ldg(&neg[((size_t)k * TL_B + b) * TL_N + d]);
            nh = min(max(nh, 0), TL_N - 1);
            vals[1 + k] = __ldg(arcb + nh * TL_N + d) * m;
        }
    }

    // 5-way block reduction: warp shuffle -> 8 warp-partials in smem -> warp 0
    __shared__ float sh[8][TL_K + 1];
    const int lane = d & 31;
    const int warp = d >> 5;
#pragma unroll
    for (int i = 0; i < TL_K + 1; i++) {
        float v = vals[i];
#pragma unroll
        for (int off = 16; off > 0; off >>= 1)
            v += __shfl_down_sync(0xffffffffu, v, off);
        if (lane == 0) sh[warp][i] = v;
    }
    __syncthreads();

    if (d < 32) {
#pragma unroll
        for (int i = 0; i < TL_K + 1; i++) {
            float v = (d < 8) ? sh[d][i] : 0.0f;
#pragma unroll
            for (int off = 4; off > 0; off >>= 1)
                v += __shfl_down_sync(0xffffffffu, v, off);
            vals[i] = v;   // lane 0 holds the block total
        }
        if (d == 0) {
            const float gold_total = vals[0];
            float loss = 0.0f;
#pragma unroll
            for (int k = 0; k < TL_K; k++)
                loss += fmaxf(TL_MARGIN - gold_total + vals[1 + k], 0.0f);
            g_partial[b] = loss;
        }
    }

    // ---- last-CTA-done final reduction ----
    __shared__ bool is_last;
    __threadfence();                       // make g_partial[b] visible GPU-wide
    __syncthreads();                       // all threads past the partial write
    if (d == 0) {
        unsigned int prev = atomicAdd(&g_done_count, 1u);
        is_last = (prev == (unsigned int)(TL_B - 1));
    }
    __syncthreads();

    if (is_last) {
        // 256 threads reduce 512 per-sentence losses (all other CTAs fenced).
        float v = g_partial[d] + g_partial[d + TL_N];
        __shared__ float rsh[8];
#pragma unroll
        for (int off = 16; off > 0; off >>= 1)
            v += __shfl_down_sync(0xffffffffu, v, off);
        if (lane == 0) rsh[warp] = v;
        __syncthreads();
        if (d < 32) {
            float w = (d < 8) ? rsh[d] : 0.0f;
#pragma unroll
            for (int off = 4; off > 0; off >>= 1)
                w += __shfl_down_sync(0xffffffffu, w, off);
            if (d == 0) {
                out[0] = w * (1.0f / (float)(TL_K * TL_B));
                atomicExch(&g_done_count, 0u);   // reset for next graph replay
            }
        }
    }
}

extern "C" void kernel_launch(void* const* d_in, const int* in_sizes, int n_in,
                              void* d_out, int out_size)
{
    const float* arc  = (const float*)d_in[0];  // arc_scores [B,N,N]
    const int*   gold = (const int*)  d_in[1];  // gold_heads [B,N]
    const int*   mask = (const int*)  d_in[2];  // mask       [B,N]
    const int*   neg  = (const int*)  d_in[3];  // neg_heads  [K,B,N]
    (void)in_sizes; (void)n_in; (void)out_size;

    tree_loss_fused_kernel<<<TL_B, TL_N>>>(arc, gold, mask, neg, (float*)d_out);
}

// round 7
// speedup vs baseline: 1.2059x; 1.2059x over previous
#include <cuda_runtime.h>

// ContrastiveTreeLoss, single-launch fused version, v2.
//
// Shapes (fixed by the problem instance):
//   arc_scores [B=512, N=256, N=256] f32
//   gold_heads [B, N] i32
//   mask       [B, N] i32
//   neg_heads  [K=4, B, N] i32
//   out        scalar f32 = mean_{k,b} relu(MARGIN - gold_total[b] + neg_total[k,b])
//
// Key optimizations vs prior rounds:
//  * neg_heads are gold_heads with ~2 swaps per sentence: lanes where nh==gh
//    reuse the gold gather value instead of issuing another scattered LDG.
//    Predicated-off lanes generate no L1tex wavefronts -> ~4x fewer wavefronts
//    (the measured bottleneck of the gather phase).
//  * Release fence executed by ONE thread per CTA (the partial writer), not all
//    256 — the all-thread gpu-scope membar was the R6 regression (+6us).
//  * Last-CTA-done final reduction keeps everything in one launch (the R5
//    second launch cost 4.3us of pure overhead).

#define TL_B 512
#define TL_N 256
#define TL_K 4
#define TL_MARGIN 2.0f

__device__ float g_partial[TL_B];
__device__ unsigned int g_done_count;   // zero-init; reset each launch by last CTA

__global__ __launch_bounds__(TL_N, 4)
void tree_loss_fused_kernel(const float* __restrict__ arc,
                            const int*   __restrict__ gold,
                            const int*   __restrict__ mask,
                            const int*   __restrict__ neg,
                            float*       __restrict__ out)
{
    const int b = blockIdx.x;     // sentence
    const int d = threadIdx.x;    // dependent index 0..N-1 (d=0 unused)
    const float* __restrict__ arcb = arc + (size_t)b * TL_N * TL_N;

    float vals[TL_K + 1];
#pragma unroll
    for (int i = 0; i < TL_K + 1; i++) vals[i] = 0.0f;

    if (d >= 1) {
        const float m = (float)__ldg(&mask[b * TL_N + d]);
        int gh = __ldg(&gold[b * TL_N + d]);
        gh = min(max(gh, 0), TL_N - 1);
        // Load all neg indices up front (coalesced streams, full MLP).
        int nh[TL_K];
#pragma unroll
        for (int k = 0; k < TL_K; k++) {
            int h = __ldg(&neg[((size_t)k * TL_B + b) * TL_N + d]);
            nh[k] = min(max(h, 0), TL_N - 1);
        }
        const float gv = __ldg(arcb + gh * TL_N + d);   // arc[b, gh, d]
        vals[0] = gv * m;
#pragma unroll
        for (int k = 0; k < TL_K; k++) {
            // ~98% of lanes have nh==gh (negatives = gold with 2 swaps).
            // Predicated LDG on the rare differing lanes only.
            float nv = (nh[k] == gh) ? gv : __ldg(arcb + nh[k] * TL_N + d);
            vals[1 + k] = nv * m;
        }
    }

    // 5-way block reduction: warp shuffle -> 8 warp-partials in smem -> warp 0
    __shared__ float sh[8][TL_K + 1];
    const int lane = d & 31;
    const int warp = d >> 5;
#pragma unroll
    for (int i = 0; i < TL_K + 1; i++) {
        float v = vals[i];
#pragma unroll
        for (int off = 16; off > 0; off >>= 1)
            v += __shfl_down_sync(0xffffffffu, v, off);
        if (lane == 0) sh[warp][i] = v;
    }
    __syncthreads();

    __shared__ bool is_last;
    if (d < 32) {
#pragma unroll
        for (int i = 0; i < TL_K + 1; i++) {
            float v = (d < 8) ? sh[d][i] : 0.0f;
#pragma unroll
            for (int off = 4; off > 0; off >>= 1)
                v += __shfl_down_sync(0xffffffffu, v, off);
            vals[i] = v;   // lane 0 holds the block total
        }
        if (d == 0) {
            const float gold_total = vals[0];
            float loss = 0.0f;
#pragma unroll
            for (int k = 0; k < TL_K; k++)
                loss += fmaxf(TL_MARGIN - gold_total + vals[1 + k], 0.0f);
            g_partial[b] = loss;
            __threadfence();   // release: order the store before the atomic
            unsigned int prev = atomicAdd(&g_done_count, 1u);
            is_last = (prev == (unsigned int)(TL_B - 1));
        }
    }
    __syncthreads();

    if (is_last) {
        if (d == 0) __threadfence();   // acquire: see all writers' stores
        __syncthreads();
        // 256 threads reduce 512 per-sentence losses (all in L2 by now).
        float v = g_partial[d] + g_partial[d + TL_N];
        __shared__ float rsh[8];
#pragma unroll
        for (int off = 16; off > 0; off >>= 1)
            v += __shfl_down_sync(0xffffffffu, v, off);
        if (lane == 0) rsh[warp] = v;
        __syncthreads();
        if (d < 32) {
            float w = (d < 8) ? rsh[d] : 0.0f;
#pragma unroll
            for (int off = 4; off > 0; off >>= 1)
                w += __shfl_down_sync(0xffffffffu, w, off);
            if (d == 0) {
                out[0] = w * (1.0f / (float)(TL_K * TL_B));
                atomicExch(&g_done_count, 0u);   // reset for next graph replay
            }
        }
    }
}

extern "C" void kernel_launch(void* const* d_in, const int* in_sizes, int n_in,
                              void* d_out, int out_size)
{
    const float* arc  = (const float*)d_in[0];  // arc_scores [B,N,N]
    const int*   gold = (const int*)  d_in[1];  // gold_heads [B,N]
    const int*   mask = (const int*)  d_in[2];  // mask       [B,N]
    const int*   neg  = (const int*)  d_in[3];  // neg_heads  [K,B,N]
    (void)in_sizes; (void)n_in; (void)out_size;

    tree_loss_fused_kernel<<<TL_B, TL_N>>>(arc, gold, mask, neg, (float*)d_out);
}